// round 7
// baseline (speedup 1.0000x reference)
#include <cuda_runtime.h>

// CapsuleLayer dynamic routing. C=10,B=128,N=1152,IN=8,OUT=16, 3 iters.
//   1) transpose W -> Wt4[c][j][n] (n innermost): coalesced phase-A loads.
//   2) fused priors + routing, one CTA per (c, 4 batches), 576 threads.
// TBATCH=4 halves CTA count -> W slab (590KB, same for all CTAs of a c)
// crosses each SM's L1 crossbar half as many times. Phase A computes the
// OUT dim in 2 halves to keep registers under the 112 cap. Shift-free
// softmax + fused logit-update/accumulation sweeps (exact).

#define CCAP   10
#define BD     128
#define ND     1152
#define OUTD   16
#define HALF   576
#define THREADS 576
#define NWARPS  18
#define NBLOCKS (CCAP * BD / 4)   // 320

// transposed weights scratch: 10*32*1152 float4 = 5.9 MB
__device__ float4 g_Wt[CCAP * 32 * ND];

__global__ void transpose_W_kernel(const float4* __restrict__ W4)
{
    int idx = blockIdx.x * blockDim.x + threadIdx.x;
    if (idx >= CCAP * 32 * ND) return;
    int n  = idx % ND;
    int t  = idx / ND;
    int j  = t % 32;
    int c  = t / 32;
    g_Wt[idx] = W4[((size_t)c * ND + n) * 32 + j];
}

// shared memory layout (floats)
#define PRI_SZ    (4 * 16 * HALF)          // 36864 : pri_s[bb][o][n]  (rep1)
#define VRED_OFF  PRI_SZ
#define VRED_SZ   (NWARPS * 64)            // [18][2 pairs][32]
#define SPRED_OFF (VRED_OFF + VRED_SZ)
#define OUTV_OFF  (SPRED_OFF + 4 * NWARPS)
#define SMEM_FLOATS (OUTV_OFF + 64)
#define SMEM_BYTES  (SMEM_FLOATS * 4)      // 152,608 B

__global__ __launch_bounds__(THREADS, 1)
void caps_routing_kernel(const float* __restrict__ x,
                         float* __restrict__ out)
{
    extern __shared__ float sm[];
    float* pri_s = sm;                 // [4][16][HALF]
    float* vred  = sm + VRED_OFF;      // [18][2][32]
    float* spred = sm + SPRED_OFF;     // [18][4]
    float* outv  = sm + OUTV_OFF;      // [4][16]

    const int tid  = threadIdx.x;
    const int lane = tid & 31;
    const int w    = tid >> 5;           // 0..17
    const int c    = blockIdx.x >> 5;    // /32
    const int b0   = (blockIdx.x & 31) * 4;

    const float4* __restrict__ X4 = (const float4*)x;

    // ---------------- Phase A: priors, OUT-halved, rep1 first ----------------
    float priA[4][16];

    #pragma unroll
    for (int rr = 0; rr < 2; rr++) {
        const int rep = 1 - rr;          // rep1 (smem) first, rep0 (regs) last
        const int n = tid + rep * HALF;

        // x for 4 batches, held across both o-halves
        float xs[4][8];
        #pragma unroll
        for (int bb = 0; bb < 4; bb++) {
            float4 u0 = X4[((size_t)(b0 + bb) * ND + n) * 2 + 0];
            float4 u1 = X4[((size_t)(b0 + bb) * ND + n) * 2 + 1];
            xs[bb][0]=u0.x; xs[bb][1]=u0.y; xs[bb][2]=u0.z; xs[bb][3]=u0.w;
            xs[bb][4]=u1.x; xs[bb][5]=u1.y; xs[bb][6]=u1.z; xs[bb][7]=u1.w;
        }

        #pragma unroll
        for (int h = 0; h < 2; h++) {
            float acc[4][8];
            #pragma unroll
            for (int bb = 0; bb < 4; bb++)
                #pragma unroll
                for (int k = 0; k < 8; k++) acc[bb][k] = 0.f;

            const float4* wp = g_Wt + (size_t)c * 32 * ND + (size_t)(2 * h) * ND + n;
            #pragma unroll
            for (int i = 0; i < 8; i++) {
                #pragma unroll
                for (int qq = 0; qq < 2; qq++) {
                    float4 wv = wp[(size_t)(i * 4 + qq) * ND];
                    #pragma unroll
                    for (int bb = 0; bb < 4; bb++) {
                        const float xv = xs[bb][i];
                        acc[bb][qq*4+0] += xv * wv.x;
                        acc[bb][qq*4+1] += xv * wv.y;
                        acc[bb][qq*4+2] += xv * wv.z;
                        acc[bb][qq*4+3] += xv * wv.w;
                    }
                }
            }
            if (rep == 1) {
                #pragma unroll
                for (int bb = 0; bb < 4; bb++)
                    #pragma unroll
                    for (int k = 0; k < 8; k++)
                        pri_s[(bb * 16 + 8 * h + k) * HALF + tid] = acc[bb][k];
            } else {
                #pragma unroll
                for (int bb = 0; bb < 4; bb++)
                    #pragma unroll
                    for (int k = 0; k < 8; k++)
                        priA[bb][8 * h + k] = acc[bb][k];
            }
        }
    }
    __syncthreads();

    // logits [batch][rep]
    float lg[4][2];
    #pragma unroll
    for (int bb = 0; bb < 4; bb++) { lg[bb][0] = 0.f; lg[bb][1] = 0.f; }

    // ---------------- Phase B: 3 fused routing sweeps ----------------
    #pragma unroll 1
    for (int it = 0; it < 3; it++) {
        #pragma unroll
        for (int pr = 0; pr < 2; pr++) {
            const int ba = pr * 2, bv = pr * 2 + 1;
            const float* __restrict__ pa = pri_s + (ba * 16) * HALF + tid;
            const float* __restrict__ pb = pri_s + (bv * 16) * HALF + tid;

            float v0[16], v1[16];
            float sp0 = 0.f, sp1 = 0.f;

            if (it == 0) {
                // logits == 0: exactly uniform attention; S = ND.
                #pragma unroll
                for (int o = 0; o < 16; o++) {
                    v0[o] = priA[ba][o] + pa[o * HALF];
                    v1[o] = priA[bv][o] + pb[o * HALF];
                }
            } else {
                // batch ba: dot pass (stash smem row in v0), then combine
                float d0 = 0.f, d1 = 0.f;
                #pragma unroll
                for (int o = 0; o < 16; o++) {
                    float pv = pa[o * HALF];
                    v0[o] = pv;
                    d0 += outv[ba * 16 + o] * priA[ba][o];
                    d1 += outv[ba * 16 + o] * pv;
                }
                lg[ba][0] += d0; lg[ba][1] += d1;
                float e0 = __expf(lg[ba][0]);
                float e1 = __expf(lg[ba][1]);
                sp0 = e0 + e1;
                #pragma unroll
                for (int o = 0; o < 16; o++)
                    v0[o] = e0 * priA[ba][o] + e1 * v0[o];

                // batch bv
                d0 = 0.f; d1 = 0.f;
                #pragma unroll
                for (int o = 0; o < 16; o++) {
                    float pv = pb[o * HALF];
                    v1[o] = pv;
                    d0 += outv[bv * 16 + o] * priA[bv][o];
                    d1 += outv[bv * 16 + o] * pv;
                }
                lg[bv][0] += d0; lg[bv][1] += d1;
                e0 = __expf(lg[bv][0]);
                e1 = __expf(lg[bv][1]);
                sp1 = e0 + e1;
                #pragma unroll
                for (int o = 0; o < 16; o++)
                    v1[o] = e0 * priA[bv][o] + e1 * v1[o];
            }

            // batch-merging component-splitting warp reduce (31 shfl):
            // bit-16 merges (ba|bv); bits 8/4/2/1 split components.
            float v[16];
            #pragma unroll
            for (int k = 0; k < 16; k++) {
                float s = (lane & 16) ? v0[k] : v1[k];
                float r = __shfl_xor_sync(0xffffffffu, s, 16);
                v[k] = ((lane & 16) ? v1[k] : v0[k]) + r;
            }
            #pragma unroll
            for (int k = 0; k < 8; k++) {
                float s = (lane & 8) ? v[k] : v[k + 8];
                float r = __shfl_xor_sync(0xffffffffu, s, 8);
                v[k] = ((lane & 8) ? v[k + 8] : v[k]) + r;
            }
            #pragma unroll
            for (int k = 0; k < 4; k++) {
                float s = (lane & 4) ? v[k] : v[k + 4];
                float r = __shfl_xor_sync(0xffffffffu, s, 4);
                v[k] = ((lane & 4) ? v[k + 4] : v[k]) + r;
            }
            #pragma unroll
            for (int k = 0; k < 2; k++) {
                float s = (lane & 2) ? v[k] : v[k + 2];
                float r = __shfl_xor_sync(0xffffffffu, s, 2);
                v[k] = ((lane & 2) ? v[k + 2] : v[k]) + r;
            }
            {
                float s = (lane & 1) ? v[0] : v[1];
                float r = __shfl_xor_sync(0xffffffffu, s, 1);
                v[0] = ((lane & 1) ? v[1] : v[0]) + r;
            }
            vred[w * 64 + pr * 32 + lane] = v[0];

            if (it > 0) {   // sp: merge batches then butterfly
                float s = (lane & 16) ? sp0 : sp1;
                float r = __shfl_xor_sync(0xffffffffu, s, 16);
                float sp = ((lane & 16) ? sp1 : sp0) + r;
                #pragma unroll
                for (int d = 8; d; d >>= 1)
                    sp += __shfl_xor_sync(0xffffffffu, sp, d);
                if ((lane & 15) == 0) spred[w * 4 + ba + (lane >> 4)] = sp;
            }
        }
        __syncthreads();

        // --- final 18-way reduce + squash (threads 0..63: bb = tid>>4) ---
        if (tid < 64) {
            const int pr = tid >> 5, bb = tid >> 4, comp = tid & 15;
            float O = 0.f;
            #pragma unroll
            for (int j = 0; j < NWARPS; j++) O += vred[j * 64 + pr * 32 + (tid & 31)];
            float S;
            if (it == 0) {
                S = (float)ND;
            } else {
                S = 0.f;
                #pragma unroll
                for (int j = 0; j < NWARPS; j++) S += spred[j * 4 + bb];
            }
            float t = O / S;
            float sq = t * t;
            #pragma unroll
            for (int d = 8; d; d >>= 1)
                sq += __shfl_xor_sync(0xffffffffu, sq, d);
            float scale = sq / ((1.f + sq) * sqrtf(sq + 1e-8f));
            float val = t * scale;
            outv[tid] = val;
            if (it == 2)
                out[((size_t)(c * BD + b0 + bb)) * OUTD + comp] = val;
        }
        __syncthreads();
    }
}

extern "C" void kernel_launch(void* const* d_in, const int* in_sizes, int n_in,
                              void* d_out, int out_size)
{
    const float* x = (const float*)d_in[0];
    const float* W = (const float*)d_in[1];
    // defensive: identify by size (x: 1,179,648 ; W: 1,474,560)
    if (n_in >= 2 && in_sizes[0] == CCAP * ND * 8 * OUTD) {
        x = (const float*)d_in[1];
        W = (const float*)d_in[0];
    }
    float* out = (float*)d_out;

    const int ttotal = CCAP * 32 * ND;
    transpose_W_kernel<<<(ttotal + 255) / 256, 256>>>((const float4*)W);

    cudaFuncSetAttribute(caps_routing_kernel,
                         cudaFuncAttributeMaxDynamicSharedMemorySize, SMEM_BYTES);
    caps_routing_kernel<<<NBLOCKS, THREADS, SMEM_BYTES>>>(x, out);
}